// round 13
// baseline (speedup 1.0000x reference)
#include <cuda_runtime.h>
#include <math.h>
#include <stdint.h>

#define NSAMP  8
#define NEXP   256
#define NMARK  10
#define KBOUND 40
#define NEV    20
#define NTAB   2048

// overlapped-pair table: g_tab[ev][i] = { f(c_i), f(c_{i+1}) },  c_i = -1 + i*h
__device__ float2 g_tab[NEV * NTAB];   // 327 KB, L2-resident

// cos with explicit Cody-Waite reduction by 2*pi, then MUFU cos.
__device__ __forceinline__ float cos_cw(float t) {
    const float INV2PI   = 0.15915494309189535f;
    const float TWOPI_HI = 6.2831854820251465f;
    const float TWOPI_LO = -1.7484555e-07f;
    float k = rintf(t * INV2PI);
    float r = fmaf(-k, TWOPI_HI, t);
    r = fmaf(-k, TWOPI_LO, r);
    return __cosf(r);
}

// exact-path sum_m softplus (table build only)
__device__ __forceinline__ float total_intensity_reg(float c,
                                                     const float* __restrict__ c0,
                                                     const float* __restrict__ sc) {
    float lin = 0.0f, prod = 1.0f;
#pragma unroll
    for (int m = 0; m < NMARK; m++) {
        float x = fmaf(sc[m], c, c0[m]);
        lin += fmaxf(x, 0.0f);
        prod *= (1.0f + __expf(-fabsf(x)));
    }
    return lin + __logf(prod);
}

// table lookup with linear interpolation; c in [-1,1]
__device__ __forceinline__ float total_lookup(float c, const float2* __restrict__ tab) {
    float idx_f = (c + 1.0f) * ((float)(NTAB - 1) * 0.5f);
    int   i     = (int)idx_f;
    i = max(0, min(i, NTAB - 2));
    float frac  = idx_f - (float)i;
    float2 p = tab[i];
    return fmaf(frac, p.y - p.x, p.x);
}

// detect int64 vs int32 encoding of event_seq, return event id for `row`.
__device__ __forceinline__ int load_event(const int* __restrict__ ev_w,
                                          int row, int lane) {
    int a = 0;
    if (lane < NMARK) a = ev_w[2 * lane + 1] | ev_w[2 * (lane + NMARK) + 1];
    unsigned ball = __ballot_sync(0xffffffffu, a != 0);
    return (ball == 0u) ? ev_w[2 * row] : ev_w[row];
}

// ---- kernel T: build intensity table for all 20 event types ----
__global__ void __launch_bounds__(256) table_kernel(
    const float* __restrict__ emb,
    const float* __restrict__ scale,
    const float* __restrict__ bias)
{
    const int idx = blockIdx.x * 256 + threadIdx.x;   // 20*2048 entries
    const int ev  = idx / NTAB;
    const int i   = idx % NTAB;

    float c0[NMARK], sc[NMARK];
#pragma unroll
    for (int m = 0; m < NMARK; m++) {
        c0[m] = emb[ev * NMARK + m] + bias[m];
        sc[m] = scale[m];
    }
    const float h   = 2.0f / (float)(NTAB - 1);
    const float c0f = fmaf((float)i, h, -1.0f);
    const int   i1  = (i + 1 < NTAB) ? i + 1 : i;
    const float c1f = fmaf((float)i1, h, -1.0f);

    float2 v;
    v.x = total_intensity_reg(c0f, c0, sc);
    v.y = total_intensity_reg(c1f, c0, sc);
    g_tab[idx] = v;

    __threadfence();
    cudaTriggerProgrammaticLaunchCompletion();
}

// ---- sampler: one WARP per row; warps fully independent, no block barrier ----
__global__ void __launch_bounds__(128, 16) sampler_kernel(
    const float* __restrict__ time_seq,
    const float* __restrict__ dt_seq,
    const int*   __restrict__ ev_w,
    const float* __restrict__ exp_raw,
    const float* __restrict__ unif,
    float* __restrict__ out_res,
    float* __restrict__ out_w,
    int write_w, int n_rows)
{
    const int lane = threadIdx.x & 31;
    const int wrp  = threadIdx.x >> 5;                  // 0..3
    const int row  = blockIdx.x * 4 + wrp;

    // per-warp private slices: no cross-warp synchronization ever
    __shared__ __align__(16) float s_exr[4][NEXP];
    __shared__ __align__(16) float s_tot[4][NEXP];

    if (row >= n_rows) { cudaGridDependencySynchronize(); return; }

    // ======== PDL preamble: independent of the table ========
    // lane owns candidates 8*lane .. 8*lane+7 (two streaming LDG.128)
    const float4* exrow = (const float4*)(exp_raw + (size_t)row * NEXP);
    const float4 exA = __ldcs(exrow + 2 * lane);
    const float4 exB = __ldcs(exrow + 2 * lane + 1);
    const float t0  = time_seq[row];
    const float dtv = dt_seq[row];
    const int   ev  = load_event(ev_w, row, lane);
    const float2* tab = g_tab + ev * NTAB;
    ((float4*)s_exr[wrp])[2 * lane]     = exA;
    ((float4*)s_exr[wrp])[2 * lane + 1] = exB;

    // ======== wait for table kernel ========
    cudaGridDependencySynchronize();

    // ---- boundary upper bound (exact same ops as R12) ----
    float lam = total_lookup(cos_cw(fmaf(dtv, (float)lane * (1.0f / 39.0f), t0)), tab);
    if (lane < KBOUND - 32)
        lam = fmaxf(lam, total_lookup(
            cos_cw(fmaf(dtv, (float)(lane + 32) * (1.0f / 39.0f), t0)), tab));
#pragma unroll
    for (int o = 16; o; o >>= 1)
        lam = fmaxf(lam, __shfl_xor_sync(0xffffffffu, lam, o));
    const float upper = 1.5f * lam;   // OVER_SAMPLE_RATE

    // ---- phase 1: 8 candidates per lane via table ----
    {
        float4 tA, tB;
        tA.x = total_lookup(cos_cw(t0 + __fdividef(exA.x, upper)), tab);
        tA.y = total_lookup(cos_cw(t0 + __fdividef(exA.y, upper)), tab);
        tA.z = total_lookup(cos_cw(t0 + __fdividef(exA.z, upper)), tab);
        tA.w = total_lookup(cos_cw(t0 + __fdividef(exA.w, upper)), tab);
        ((float4*)s_tot[wrp])[2 * lane] = tA;
        tB.x = total_lookup(cos_cw(t0 + __fdividef(exB.x, upper)), tab);
        tB.y = total_lookup(cos_cw(t0 + __fdividef(exB.y, upper)), tab);
        tB.z = total_lookup(cos_cw(t0 + __fdividef(exB.z, upper)), tab);
        tB.w = total_lookup(cos_cw(t0 + __fdividef(exB.w, upper)), tab);
        ((float4*)s_tot[wrp])[2 * lane + 1] = tB;
    }
    __syncwarp();   // warp-local smem visibility; no block barrier anywhere

    // ---- phase 2: this warp scans all 8 slots of its row ----
    const float4* pe = (const float4*)s_exr[wrp];
    const float4* pt = (const float4*)s_tot[wrp];
    const float*  ubase = unif + (size_t)row * (NSAMP * NEXP);
#pragma unroll
    for (int j = 0; j < NSAMP; j++) {
        const float4* su = (const float4*)(ubase + (size_t)j * NEXP);
        float m = INFINITY;
#pragma unroll
        for (int half = 0; half < 2; half++) {
            int q = 32 * half + lane;
            float4 u4 = __ldcs(su + q);   // streaming: don't evict the table
            float4 e4 = pe[q];
            float4 t4 = pt[q];
            if (u4.x * upper < t4.x) m = fminf(m, e4.x);
            if (u4.y * upper < t4.y) m = fminf(m, e4.y);
            if (u4.z * upper < t4.z) m = fminf(m, e4.z);
            if (u4.w * upper < t4.w) m = fminf(m, e4.w);
        }
#pragma unroll
        for (int o = 16; o; o >>= 1)
            m = fminf(m, __shfl_xor_sync(0xffffffffu, m, o));
        if (lane == 0) {
            // min over exr, then one divide == the winning candidate's ex bits
            float r = isinf(m) ? 5.0f : fminf(__fdividef(m, upper), 1e5f);
            out_res[row * NSAMP + j] = r;
            if (write_w) out_w[row * NSAMP + j] = 0.125f;
        }
    }
}

extern "C" void kernel_launch(void* const* d_in, const int* in_sizes, int n_in,
                              void* d_out, int out_size) {
    const float* time_seq = (const float*)d_in[0];
    const float* dt_seq   = (const float*)d_in[1];
    const int*   ev_w     = (const int*)  d_in[2];
    const float* exp_raw  = (const float*)d_in[3];
    const float* unif     = (const float*)d_in[4];
    const float* emb      = (const float*)d_in[5];
    const float* scale    = (const float*)d_in[6];
    const float* bias     = (const float*)d_in[7];

    const int n_rows    = in_sizes[0];          // B*S = 16384
    const int res_elems = n_rows * NSAMP;
    float* res  = (float*)d_out;
    float* wout = res + res_elems;
    const int write_w = (out_size >= 2 * res_elems) ? 1 : 0;

    table_kernel<<<(NEV * NTAB) / 256, 256>>>(emb, scale, bias);

    // sampler overlaps its preamble with the table build via PDL.
    cudaLaunchConfig_t cfg = {};
    cfg.gridDim  = dim3((unsigned)((n_rows + 3) / 4), 1, 1);
    cfg.blockDim = dim3(128, 1, 1);
    cfg.dynamicSmemBytes = 0;
    cfg.stream = 0;
    cudaLaunchAttribute attr[1];
    attr[0].id = cudaLaunchAttributeProgrammaticStreamSerialization;
    attr[0].val.programmaticStreamSerializationAllowed = 1;
    cfg.attrs = attr;
    cfg.numAttrs = 1;
    cudaLaunchKernelEx(&cfg, sampler_kernel,
                       time_seq, dt_seq, ev_w, exp_raw, unif,
                       res, wout, write_w, n_rows);
}